// round 1
// baseline (speedup 1.0000x reference)
#include <cuda_runtime.h>
#include <math.h>
#include <stdint.h>

// Problem constants (shapes are fixed by the dataset)
#define BATCH   16
#define CH      256
#define HH      64
#define WW2     64
#define TOKENS  (BATCH*HH*WW2)     // 65536
#define HID     1024
#define NHEAD   8
#define HDIM    32
#define WS      8
#define NWIN    8                   // windows per side
#define NTOK    64                  // tokens per window

// ---------------- scratch (device globals; allocation-free) ----------------
__device__ float g_xf [TOKENS*CH];   // shortcut, token-major
__device__ float g_xnw[TOKENS*CH];   // LN1 out, windowed-row-major
__device__ float g_q  [TOKENS*CH];   // [win][head][pos][hd]
__device__ float g_k  [TOKENS*CH];
__device__ float g_v  [TOKENS*CH];
__device__ float g_att[TOKENS*CH];   // attn out (+gaze), windowed-row-major
__device__ float g_img[TOKENS*CH];   // folded image, NHWC
__device__ float g_xf2[TOKENS*CH];   // after proj residual, token-major
__device__ float g_ln2[TOKENS*CH];   // LN2 out, token-major
__device__ float g_h1 [TOKENS*HID];  // MLP hidden
__device__ float g_bias[NHEAD*NTOK*NTOK];

// ---------------- relative position bias prep ----------------
__global__ void bias_kernel(const float* __restrict__ rpb) {
    int idx = blockIdx.x*256 + threadIdx.x;          // 8*64*64 = 32768
    int h_ = idx >> 12, n = (idx >> 6) & 63, m = idx & 63;
    int di = (n >> 3) - (m >> 3) + 7;
    int dj = (n & 7)  - (m & 7)  + 7;
    g_bias[idx] = rpb[(di*15 + dj)*NHEAD + h_];
}

// ---------------- LayerNorm 1 (reads NCHW x, writes shortcut + windowed LN) ----------------
__global__ __launch_bounds__(256) void ln1_kernel(const float* __restrict__ x,
                                                  const float* __restrict__ gw,
                                                  const float* __restrict__ gb) {
    int t = blockIdx.x, c = threadIdx.x;
    int b = t >> 12, hw = t & 4095, h = hw >> 6, w = hw & 63;
    float val = x[((size_t)(b*CH + c) << 12) + hw];

    __shared__ float sh1[8], sh2[8], sres[2];
    float s = val, s2 = val*val;
    #pragma unroll
    for (int o = 16; o; o >>= 1) { s += __shfl_xor_sync(~0u, s, o); s2 += __shfl_xor_sync(~0u, s2, o); }
    int lane = c & 31, wrp = c >> 5;
    if (!lane) { sh1[wrp] = s; sh2[wrp] = s2; }
    __syncthreads();
    if (!wrp) {
        s  = lane < 8 ? sh1[lane] : 0.f;
        s2 = lane < 8 ? sh2[lane] : 0.f;
        #pragma unroll
        for (int o = 4; o; o >>= 1) { s += __shfl_xor_sync(~0u, s, o); s2 += __shfl_xor_sync(~0u, s2, o); }
        if (!lane) { sres[0] = s; sres[1] = s2; }
    }
    __syncthreads();
    float mean = sres[0] * (1.f/CH);
    float var  = sres[1] * (1.f/CH) - mean*mean;
    float nv = (val - mean) * rsqrtf(var + 1e-5f) * gw[c] + gb[c];

    g_xf[(size_t)t*CH + c] = val;
    int wh = h >> 3, ii = h & 7, ww = w >> 3, jj = w & 7;
    int r = ((b*64 + wh*8 + ww) << 6) + (ii << 3) + jj;
    g_xnw[(size_t)r*CH + c] = nv;
}

// ---------------- LayerNorm 2 (token-major in/out) ----------------
__global__ __launch_bounds__(256) void ln2_kernel(const float* __restrict__ gw,
                                                  const float* __restrict__ gb) {
    int t = blockIdx.x, c = threadIdx.x;
    float val = g_xf2[(size_t)t*CH + c];

    __shared__ float sh1[8], sh2[8], sres[2];
    float s = val, s2 = val*val;
    #pragma unroll
    for (int o = 16; o; o >>= 1) { s += __shfl_xor_sync(~0u, s, o); s2 += __shfl_xor_sync(~0u, s2, o); }
    int lane = c & 31, wrp = c >> 5;
    if (!lane) { sh1[wrp] = s; sh2[wrp] = s2; }
    __syncthreads();
    if (!wrp) {
        s  = lane < 8 ? sh1[lane] : 0.f;
        s2 = lane < 8 ? sh2[lane] : 0.f;
        #pragma unroll
        for (int o = 4; o; o >>= 1) { s += __shfl_xor_sync(~0u, s, o); s2 += __shfl_xor_sync(~0u, s2, o); }
        if (!lane) { sres[0] = s; sres[1] = s2; }
    }
    __syncthreads();
    float mean = sres[0] * (1.f/CH);
    float var  = sres[1] * (1.f/CH) - mean*mean;
    g_ln2[(size_t)t*CH + c] = (val - mean) * rsqrtf(var + 1e-5f) * gw[c] + gb[c];
}

// ---------------- generic SGEMM: C[m][n] = sum_k A[m][k]*W[n][k], epilogue functor --------
// BM=BN=128, BK=8, 256 threads, 8x8 register tile. M,N multiples of 128; K multiple of 8.
template <class Epi>
__global__ __launch_bounds__(256) void sgemm_kernel(const float* __restrict__ A,
                                                    const float* __restrict__ W,
                                                    int K, Epi epi) {
    __shared__ float As[8][128];
    __shared__ float Bs[8][128];
    int bm = blockIdx.y << 7, bn = blockIdx.x << 7;
    int tid = threadIdx.x;
    int tx = tid & 15, ty = tid >> 4;
    int lrow = tid >> 1, lcol = (tid & 1) << 2;
    const float* Ap = A + (size_t)(bm + lrow)*K + lcol;
    const float* Wp = W + (size_t)(bn + lrow)*K + lcol;
    float acc[8][8] = {};
    for (int k0 = 0; k0 < K; k0 += 8) {
        float4 av = *(const float4*)(Ap + k0);
        float4 bv = *(const float4*)(Wp + k0);
        As[lcol+0][lrow] = av.x; As[lcol+1][lrow] = av.y;
        As[lcol+2][lrow] = av.z; As[lcol+3][lrow] = av.w;
        Bs[lcol+0][lrow] = bv.x; Bs[lcol+1][lrow] = bv.y;
        Bs[lcol+2][lrow] = bv.z; Bs[lcol+3][lrow] = bv.w;
        __syncthreads();
        #pragma unroll
        for (int kk = 0; kk < 8; kk++) {
            float ar[8], br[8];
            #pragma unroll
            for (int i = 0; i < 8; i++) ar[i] = As[kk][(ty << 3) + i];
            #pragma unroll
            for (int j = 0; j < 8; j++) br[j] = Bs[kk][(tx << 3) + j];
            #pragma unroll
            for (int i = 0; i < 8; i++)
                #pragma unroll
                for (int j = 0; j < 8; j++)
                    acc[i][j] = fmaf(ar[i], br[j], acc[i][j]);
        }
        __syncthreads();
    }
    #pragma unroll
    for (int i = 0; i < 8; i++)
        #pragma unroll
        for (int j = 0; j < 8; j++)
            epi(bm + (ty << 3) + i, bn + (tx << 3) + j, acc[i][j]);
}

// epilogues ----------------------------------------------------------------
struct EpiQKV {
    const float* bias;  // 768
    __device__ void operator()(int r, int c, float acc) const {
        float val = acc + bias[c];
        int part = c >> 8, head = (c >> 5) & 7, d = c & 31;
        int win = r >> 6, pos = r & 63;
        size_t o = (size_t)(win*NHEAD + head)*2048 + pos*32 + d;
        if (part == 0)      g_q[o] = val * 4.0f;   // qk_scale
        else if (part == 1) g_k[o] = val;
        else                g_v[o] = val;
    }
};
struct EpiProj {
    const float* bias;  // 256
    __device__ void operator()(int r, int c, float acc) const {
        float val = acc + bias[c];
        int win = r >> 6, pos = r & 63;
        int b = win >> 6, wh = (win >> 3) & 7, ww = win & 7;
        int ii = pos >> 3, jj = pos & 7;
        int t = (b << 12) + ((wh*8 + ii) << 6) + ww*8 + jj;
        size_t o = (size_t)t*CH + c;
        g_xf2[o] = g_xf[o] + val;
    }
};
struct EpiFC1 {
    const float* bias;  // 1024
    __device__ void operator()(int r, int c, float acc) const {
        float x = acc + bias[c];
        g_h1[(size_t)r*HID + c] = 0.5f * x * (1.0f + erff(x * 0.70710678118654752f));
    }
};
struct EpiFC2 {
    const float* bias;  // 256
    float* out;
    __device__ void operator()(int r, int c, float acc) const {
        float val = acc + bias[c] + g_xf2[(size_t)r*CH + c];
        int b = r >> 12, hw = r & 4095;
        out[((size_t)(b*CH + c) << 12) + hw] = val;  // (B,C,H,W)
    }
};

// ---------------- per-(window,head) attention ----------------
__global__ __launch_bounds__(256) void attn_kernel() {
    int win = blockIdx.x >> 3, head = blockIdx.x & 7;
    __shared__ float sq[64][32];
    __shared__ float sk[64][33];
    __shared__ float sv[64][32];
    __shared__ float sp[64][65];
    size_t base = (size_t)(win*NHEAD + head) * 2048;
    int tid = threadIdx.x;
    for (int i = tid; i < 2048; i += 256) {
        int rr = i >> 5, dd = i & 31;
        sq[rr][dd] = g_q[base + i];
        sk[rr][dd] = g_k[base + i];
        sv[rr][dd] = g_v[base + i];
    }
    __syncthreads();
    {   // S = q k^T + bias
        int n = tid >> 2, mg = tid & 3;
        float qreg[32];
        #pragma unroll
        for (int d = 0; d < 32; d++) qreg[d] = sq[n][d];
        const float* bb = g_bias + head*4096 + n*64;
        for (int mm = 0; mm < 16; mm++) {
            int m = mg + (mm << 2);
            float acc = 0.f;
            #pragma unroll
            for (int d = 0; d < 32; d++) acc = fmaf(qreg[d], sk[m][d], acc);
            sp[n][m] = acc + bb[m];
        }
    }
    __syncthreads();
    int lane = tid & 31, wrp = tid >> 5;
    #pragma unroll
    for (int rr2 = 0; rr2 < 8; rr2++) {   // softmax rows
        int row = (wrp << 3) + rr2;
        float a0 = sp[row][lane], a1 = sp[row][lane + 32];
        float mx = fmaxf(a0, a1);
        #pragma unroll
        for (int o = 16; o; o >>= 1) mx = fmaxf(mx, __shfl_xor_sync(~0u, mx, o));
        float e0 = __expf(a0 - mx), e1 = __expf(a1 - mx);
        float sm = e0 + e1;
        #pragma unroll
        for (int o = 16; o; o >>= 1) sm += __shfl_xor_sync(~0u, sm, o);
        float inv = 1.0f / sm;
        sp[row][lane] = e0 * inv; sp[row][lane + 32] = e1 * inv;
    }
    __syncthreads();
    float acc[8] = {};
    for (int m = 0; m < 64; m++) {        // O = P V
        float vv = sv[m][lane];
        #pragma unroll
        for (int nn = 0; nn < 8; nn++)
            acc[nn] = fmaf(sp[(wrp << 3) + nn][m], vv, acc[nn]);
    }
    float* ob = g_att + (size_t)win*NTOK*CH + head*HDIM;
    #pragma unroll
    for (int nn = 0; nn < 8; nn++)
        ob[(size_t)((wrp << 3) + nn)*CH + lane] = acc[nn];
}

// ---------------- fold: v -> NHWC image ----------------
__global__ __launch_bounds__(256) void fold_kernel() {
    size_t idx = (size_t)blockIdx.x*256 + threadIdx.x;   // 16,777,216
    int ch = idx & 255;
    int Cc = (int)((idx >> 8) & 63);
    int R  = (int)((idx >> 14) & 63);
    int b  = (int)(idx >> 20);
    int win  = (b << 6) + ((R & 7) << 3) + (Cc & 7);
    int pos  = ((R >> 3) << 3) + (Cc >> 3);
    int head = ch >> 5, hd = ch & 31;
    g_img[idx] = g_v[(size_t)(win*NHEAD + head)*2048 + pos*32 + hd];
}

// ---------------- depthwise 9x9 conv + unfold, accumulated into g_att ----------------
__global__ __launch_bounds__(256) void gaze_conv_kernel(const float* __restrict__ gw,
                                                        const float* __restrict__ gb) {
    int bidx = blockIdx.x;                 // 16 * 64 * 8 = 8192 blocks
    int cc   = bidx & 7;                   // channel chunk (32 ch)
    int tile = (bidx >> 3) & 63;           // 8x8 spatial tiles
    int b    = bidx >> 9;
    int tr = (tile >> 3) << 3;
    int tc = (tile & 7) << 3;
    int ch0 = cc << 5;

    __shared__ float sin_[16][16][32];     // input halo tile: 32 KB
    __shared__ float swt[81][32];          // weights: 10.4 KB
    int tid = threadIdx.x;

    for (int i = tid; i < 81*32; i += 256) {
        int tap = i >> 5, ch = i & 31;
        swt[tap][ch] = gw[tap*CH + ch0 + ch];
    }
    for (int i = tid; i < 16*16*32; i += 256) {
        int ch = i & 31, px = (i >> 5) & 15, py = i >> 9;
        int R = tr - 4 + py, Cc = tc - 4 + px;
        float v = 0.f;
        if (R >= 0 && R < 64 && Cc >= 0 && Cc < 64)
            v = g_img[(((size_t)((b << 6) + R) << 6) + Cc)*CH + ch0 + ch];
        sin_[py][px][ch] = v;
    }
    __syncthreads();

    int ch = tid & 31, px = tid >> 5;      // px in 0..7
    float acc[8] = {};
    #pragma unroll
    for (int dx = 0; dx < 9; dx++) {
        float col[16];
        #pragma unroll
        for (int ry = 0; ry < 16; ry++) col[ry] = sin_[ry][px + dx][ch];
        #pragma unroll
        for (int dy = 0; dy < 9; dy++) {
            float wv = swt[dy*9 + dx][ch];
            #pragma unroll
            for (int py = 0; py < 8; py++) acc[py] = fmaf(col[py + dy], wv, acc[py]);
        }
    }
    float bias = gb[ch0 + ch];
    #pragma unroll
    for (int py = 0; py < 8; py++) {
        int R = tr + py, Cc = tc + px;
        int wh = R & 7, ii = R >> 3, ww = Cc & 7, jj = Cc >> 3;
        int r = ((b*64 + wh*8 + ww) << 6) + (ii << 3) + jj;
        size_t o = (size_t)r*CH + ch0 + ch;
        g_att[o] += acc[py] + bias;        // sequential after attn_kernel
    }
}

// ---------------- host launch ----------------
extern "C" void kernel_launch(void* const* d_in, const int* in_sizes, int n_in,
                              void* d_out, int out_size) {
    int off = (n_in >= 18) ? 2 : 0;  // skip H, W scalars if present
    const float* x       = (const float*)d_in[off + 0];
    const float* norm1_g = (const float*)d_in[off + 1];
    const float* norm1_b = (const float*)d_in[off + 2];
    const float* qkv_w   = (const float*)d_in[off + 3];
    const float* qkv_b   = (const float*)d_in[off + 4];
    const float* rpb     = (const float*)d_in[off + 5];
    const float* proj_w  = (const float*)d_in[off + 6];
    const float* proj_b  = (const float*)d_in[off + 7];
    const float* gaze_w  = (const float*)d_in[off + 8];
    const float* gaze_b  = (const float*)d_in[off + 9];
    const float* norm2_g = (const float*)d_in[off + 10];
    const float* norm2_b = (const float*)d_in[off + 11];
    const float* fc1_w   = (const float*)d_in[off + 12];
    const float* fc1_b   = (const float*)d_in[off + 13];
    const float* fc2_w   = (const float*)d_in[off + 14];
    const float* fc2_b   = (const float*)d_in[off + 15];

    float *p_xnw, *p_att, *p_ln2, *p_h1;
    cudaGetSymbolAddress((void**)&p_xnw, g_xnw);
    cudaGetSymbolAddress((void**)&p_att, g_att);
    cudaGetSymbolAddress((void**)&p_ln2, g_ln2);
    cudaGetSymbolAddress((void**)&p_h1,  g_h1);

    bias_kernel<<<128, 256>>>(rpb);
    ln1_kernel<<<TOKENS, 256>>>(x, norm1_g, norm1_b);
    sgemm_kernel<<<dim3(6, 512), 256>>>(p_xnw, qkv_w, 256, EpiQKV{qkv_b});
    fold_kernel<<<TOKENS, 256>>>();
    attn_kernel<<<8192, 256>>>();
    gaze_conv_kernel<<<8192, 256>>>(gaze_w, gaze_b);
    sgemm_kernel<<<dim3(2, 512), 256>>>(p_att, proj_w, 256, EpiProj{proj_b});
    ln2_kernel<<<TOKENS, 256>>>(norm2_g, norm2_b);
    sgemm_kernel<<<dim3(8, 512), 256>>>(p_ln2, fc1_w, 256, EpiFC1{fc1_b});
    sgemm_kernel<<<dim3(2, 512), 256>>>(p_h1, fc2_w, 1024, EpiFC2{fc2_b, (float*)d_out});
}

// round 3
// speedup vs baseline: 2.3180x; 2.3180x over previous
#include <cuda_runtime.h>
#include <cuda_fp16.h>
#include <math.h>
#include <stdint.h>

// Problem constants
#define BATCH   16
#define CH      256
#define TOKENS  (BATCH*64*64)      // 65536
#define HID     1024
#define NHEAD   8
#define HDIM    32
#define NTOK    64

// ---------------- scratch (device globals; allocation-free) ----------------
__device__ float g_xf [TOKENS*CH];   // shortcut, token-major
__device__ float g_xnw[TOKENS*CH];   // LN1 out (windowed); reused as y (token-major) at the end
__device__ float g_q  [TOKENS*CH];   // [win][head][pos][hd]
__device__ float g_k  [TOKENS*CH];
__device__ float g_v  [TOKENS*CH];
__device__ float g_att[TOKENS*CH];   // attn out (+gaze), windowed-row-major
__device__ float g_img[TOKENS*CH];   // folded image, NHWC
__device__ float g_xf2[TOKENS*CH];   // after proj residual, token-major
__device__ float g_ln2[TOKENS*CH];   // LN2 out
__device__ float g_h1 [TOKENS*HID];  // MLP hidden
__device__ float g_bias[NHEAD*NTOK*NTOK];

// ============================ helpers ============================
__device__ __forceinline__ uint32_t smem_u32(const void* p) {
    uint32_t a;
    asm("{ .reg .u64 t; cvta.to.shared.u64 t, %1; cvt.u32.u64 %0, t; }" : "=r"(a) : "l"(p));
    return a;
}
__device__ __forceinline__ uint32_t f2h2(float a, float b) {
    __half2 h = __floats2half2_rn(a, b);
    return *reinterpret_cast<uint32_t*>(&h);
}
__device__ __forceinline__ void ldsm4(uint32_t (&r)[4], uint32_t addr) {
    asm volatile("ldmatrix.sync.aligned.m8n8.x4.shared.b16 {%0,%1,%2,%3}, [%4];"
                 : "=r"(r[0]), "=r"(r[1]), "=r"(r[2]), "=r"(r[3]) : "r"(addr));
}
__device__ __forceinline__ void mma16816(float* d, const uint32_t* a, uint32_t b0, uint32_t b1) {
    asm volatile("mma.sync.aligned.m16n8k16.row.col.f32.f16.f16.f32 "
                 "{%0,%1,%2,%3},{%4,%5,%6,%7},{%8,%9},{%0,%1,%2,%3};"
                 : "+f"(d[0]), "+f"(d[1]), "+f"(d[2]), "+f"(d[3])
                 : "r"(a[0]), "r"(a[1]), "r"(a[2]), "r"(a[3]), "r"(b0), "r"(b1));
}

// ============================ fp16 tensor-core GEMM ============================
// C[m][n] = sum_k A[m][k]*W[n][k]. BM=BN=128, BK=32, 256 thr (2x4 warps), warp tile 64x32.
#define LDSTR 40   // halves per smem row (80B padded stride: conflict-free ldmatrix)

template <class Epi>
__global__ __launch_bounds__(256) void hgemm(const float* __restrict__ A,
                                             const float* __restrict__ W,
                                             int K, Epi epi) {
    __shared__ __half sA[2][128 * LDSTR];
    __shared__ __half sB[2][128 * LDSTR];
    int tid = threadIdx.x, lane = tid & 31, wid = tid >> 5;
    int wm = wid >> 2, wn = wid & 3;
    int bm = blockIdx.y << 7, bn = blockIdx.x << 7;
    int lrow = tid >> 1, lk = (tid & 1) << 4;
    const float* Ag = A + (size_t)(bm + lrow) * K + lk;
    const float* Wg = W + (size_t)(bn + lrow) * K + lk;

    float acc[4][4][4] = {};
    float4 ra[4], rb[4];
    int NC = K >> 5;

    #pragma unroll
    for (int i = 0; i < 4; i++) { ra[i] = *(const float4*)(Ag + i * 4); rb[i] = *(const float4*)(Wg + i * 4); }
    {
        uint32_t u[8];
        #pragma unroll
        for (int i = 0; i < 4; i++) { u[2*i] = f2h2(ra[i].x, ra[i].y); u[2*i+1] = f2h2(ra[i].z, ra[i].w); }
        *(uint4*)&sA[0][lrow * LDSTR + lk]     = *(uint4*)&u[0];
        *(uint4*)&sA[0][lrow * LDSTR + lk + 8] = *(uint4*)&u[4];
        #pragma unroll
        for (int i = 0; i < 4; i++) { u[2*i] = f2h2(rb[i].x, rb[i].y); u[2*i+1] = f2h2(rb[i].z, rb[i].w); }
        *(uint4*)&sB[0][lrow * LDSTR + lk]     = *(uint4*)&u[0];
        *(uint4*)&sB[0][lrow * LDSTR + lk + 8] = *(uint4*)&u[4];
    }
    __syncthreads();

    for (int ic = 0; ic < NC; ic++) {
        int buf = ic & 1;
        if (ic + 1 < NC) {
            int k0 = (ic + 1) << 5;
            #pragma unroll
            for (int i = 0; i < 4; i++) {
                ra[i] = *(const float4*)(Ag + k0 + i * 4);
                rb[i] = *(const float4*)(Wg + k0 + i * 4);
            }
        }
        uint32_t baseA = smem_u32(&sA[buf][0]);
        uint32_t baseB = smem_u32(&sB[buf][0]);
        #pragma unroll
        for (int ks = 0; ks < 2; ks++) {
            uint32_t af[4][4], bf[2][4];
            #pragma unroll
            for (int mt = 0; mt < 4; mt++)
                ldsm4(af[mt], baseA + (((wm*64 + mt*16 + (lane & 15)) * LDSTR + ks*16 + (lane >> 4)*8) << 1));
            #pragma unroll
            for (int bt = 0; bt < 2; bt++)
                ldsm4(bf[bt], baseB + (((wn*32 + bt*16 + (lane & 15)) * LDSTR + ks*16 + (lane >> 4)*8) << 1));
            #pragma unroll
            for (int mt = 0; mt < 4; mt++)
                #pragma unroll
                for (int nt = 0; nt < 4; nt++)
                    mma16816(acc[mt][nt], af[mt], bf[nt>>1][nt&1], bf[nt>>1][(nt&1)+2]);
        }
        if (ic + 1 < NC) {
            __syncthreads();
            int nb = buf ^ 1;
            uint32_t u[8];
            #pragma unroll
            for (int i = 0; i < 4; i++) { u[2*i] = f2h2(ra[i].x, ra[i].y); u[2*i+1] = f2h2(ra[i].z, ra[i].w); }
            *(uint4*)&sA[nb][lrow * LDSTR + lk]     = *(uint4*)&u[0];
            *(uint4*)&sA[nb][lrow * LDSTR + lk + 8] = *(uint4*)&u[4];
            #pragma unroll
            for (int i = 0; i < 4; i++) { u[2*i] = f2h2(rb[i].x, rb[i].y); u[2*i+1] = f2h2(rb[i].z, rb[i].w); }
            *(uint4*)&sB[nb][lrow * LDSTR + lk]     = *(uint4*)&u[0];
            *(uint4*)&sB[nb][lrow * LDSTR + lk + 8] = *(uint4*)&u[4];
            __syncthreads();
        }
    }
    int g = lane >> 2, tg = lane & 3;
    #pragma unroll
    for (int mt = 0; mt < 4; mt++) {
        int M0 = bm + wm * 64 + mt * 16;
        #pragma unroll
        for (int nt = 0; nt < 4; nt++) {
            int N0 = bn + wn * 32 + nt * 8;
            float* d = acc[mt][nt];
            epi(M0 + g,     N0 + tg*2,     d[0]);
            epi(M0 + g,     N0 + tg*2 + 1, d[1]);
            epi(M0 + g + 8, N0 + tg*2,     d[2]);
            epi(M0 + g + 8, N0 + tg*2 + 1, d[3]);
        }
    }
}

// ============================ epilogues ============================
struct EpiQKV {
    const float* bias;  // 768
    __device__ void operator()(int r, int c, float acc) const {
        float val = acc + bias[c];
        int part = c >> 8, head = (c >> 5) & 7, d = c & 31;
        int win = r >> 6, pos = r & 63;
        size_t o = (size_t)(win * NHEAD + head) * 2048 + pos * 32 + d;
        if (part == 0)      g_q[o] = val * 4.0f;   // qk_scale
        else if (part == 1) g_k[o] = val;
        else {
            g_v[o] = val;
            int b = win >> 6, wh = (win >> 3) & 7, ww = win & 7;
            int ii = pos >> 3, jj = pos & 7;
            int R = ii * 8 + wh, Cc = jj * 8 + ww;
            g_img[(((size_t)((b << 6) + R) << 6) + Cc) * CH + (c - 512)] = val;
        }
    }
};
struct EpiProj {
    const float* bias;
    __device__ void operator()(int r, int c, float acc) const {
        float val = acc + bias[c];
        int win = r >> 6, pos = r & 63;
        int b = win >> 6, wh = (win >> 3) & 7, ww = win & 7;
        int ii = pos >> 3, jj = pos & 7;
        int t = (b << 12) + ((wh * 8 + ii) << 6) + ww * 8 + jj;
        size_t o = (size_t)t * CH + c;
        g_xf2[o] = g_xf[o] + val;
    }
};
struct EpiFC1 {
    const float* bias;
    __device__ void operator()(int r, int c, float acc) const {
        float x = acc + bias[c];
        g_h1[(size_t)r * HID + c] = 0.5f * x * (1.0f + erff(x * 0.70710678118654752f));
    }
};
struct EpiFC2 {
    const float* bias;
    __device__ void operator()(int r, int c, float acc) const {
        g_xnw[(size_t)r * CH + c] = acc + bias[c] + g_xf2[(size_t)r * CH + c];
    }
};

// ---------------- relative position bias prep ----------------
__global__ void bias_kernel(const float* __restrict__ rpb) {
    int idx = blockIdx.x * 256 + threadIdx.x;
    int h_ = idx >> 12, n = (idx >> 6) & 63, m = idx & 63;
    int di = (n >> 3) - (m >> 3) + 7;
    int dj = (n & 7) - (m & 7) + 7;
    g_bias[idx] = rpb[(di * 15 + dj) * NHEAD + h_];
}

// ---------------- LayerNorm 1: NCHW in (tiled transpose), shortcut + windowed LN out ----
__global__ __launch_bounds__(256) void ln1_kernel(const float* __restrict__ x,
                                                  const float* __restrict__ gw,
                                                  const float* __restrict__ gb) {
    __shared__ float tx[256][33];
    int t0 = blockIdx.x * 32;
    int b = t0 >> 12, hw0 = t0 & 4095;
    int tid = threadIdx.x;
    #pragma unroll
    for (int j = 0; j < 32; j++) {
        int idx = j * 256 + tid;
        int c = idx >> 5, i = idx & 31;
        tx[c][i] = x[((size_t)(b * CH + c) << 12) + hw0 + i];
    }
    __syncthreads();
    int lane = tid & 31, w = tid >> 5;
    #pragma unroll
    for (int q = 0; q < 4; q++) {
        int i = w * 4 + q;
        float s = 0.f, s2 = 0.f;
        #pragma unroll
        for (int k = 0; k < 8; k++) { float v = tx[lane + 32 * k][i]; s += v; s2 += v * v; }
        #pragma unroll
        for (int o = 16; o; o >>= 1) { s += __shfl_xor_sync(~0u, s, o); s2 += __shfl_xor_sync(~0u, s2, o); }
        float mean = s * (1.f / CH);
        float inv = rsqrtf(s2 * (1.f / CH) - mean * mean + 1e-5f);
        int t = t0 + i;
        int hw = hw0 + i, hh = hw >> 6, wc = hw & 63;
        int wh = hh >> 3, ii = hh & 7, ww = wc >> 3, jj = wc & 7;
        int r = ((b * 64 + wh * 8 + ww) << 6) + (ii << 3) + jj;
        #pragma unroll
        for (int k = 0; k < 8; k++) {
            int c = lane + 32 * k;
            float v = tx[c][i];
            g_xf[(size_t)t * CH + c] = v;
            g_xnw[(size_t)r * CH + c] = (v - mean) * inv * gw[c] + gb[c];
        }
    }
}

// ---------------- LayerNorm 2 ----------------
__global__ __launch_bounds__(256) void ln2_kernel(const float* __restrict__ gw,
                                                  const float* __restrict__ gb) {
    int t = blockIdx.x, c = threadIdx.x;
    float val = g_xf2[(size_t)t * CH + c];
    __shared__ float sh1[8], sh2[8], sres[2];
    float s = val, s2 = val * val;
    #pragma unroll
    for (int o = 16; o; o >>= 1) { s += __shfl_xor_sync(~0u, s, o); s2 += __shfl_xor_sync(~0u, s2, o); }
    int lane = c & 31, wrp = c >> 5;
    if (!lane) { sh1[wrp] = s; sh2[wrp] = s2; }
    __syncthreads();
    if (!wrp) {
        s = lane < 8 ? sh1[lane] : 0.f;
        s2 = lane < 8 ? sh2[lane] : 0.f;
        #pragma unroll
        for (int o = 4; o; o >>= 1) { s += __shfl_xor_sync(~0u, s, o); s2 += __shfl_xor_sync(~0u, s2, o); }
        if (!lane) { sres[0] = s; sres[1] = s2; }
    }
    __syncthreads();
    float mean = sres[0] * (1.f / CH);
    float var = sres[1] * (1.f / CH) - mean * mean;
    g_ln2[(size_t)t * CH + c] = (val - mean) * rsqrtf(var + 1e-5f) * gw[c] + gb[c];
}

// ---------------- per-(window,head) attention ----------------
__global__ __launch_bounds__(256) void attn_kernel() {
    int win = blockIdx.x >> 3, head = blockIdx.x & 7;
    __shared__ float sq[64][32];
    __shared__ float sk[64][33];
    __shared__ float sv[64][32];
    __shared__ float sp[64][65];
    size_t base = (size_t)(win * NHEAD + head) * 2048;
    int tid = threadIdx.x;
    for (int i = tid; i < 2048; i += 256) {
        int rr = i >> 5, dd = i & 31;
        sq[rr][dd] = g_q[base + i];
        sk[rr][dd] = g_k[base + i];
        sv[rr][dd] = g_v[base + i];
    }
    __syncthreads();
    {
        int n = tid >> 2, mg = tid & 3;
        float qreg[32];
        #pragma unroll
        for (int d = 0; d < 32; d++) qreg[d] = sq[n][d];
        const float* bb = g_bias + head * 4096 + n * 64;
        for (int mm = 0; mm < 16; mm++) {
            int m = mg + (mm << 2);
            float acc = 0.f;
            #pragma unroll
            for (int d = 0; d < 32; d++) acc = fmaf(qreg[d], sk[m][d], acc);
            sp[n][m] = acc + bb[m];
        }
    }
    __syncthreads();
    int lane = tid & 31, wrp = tid >> 5;
    #pragma unroll
    for (int rr2 = 0; rr2 < 8; rr2++) {
        int row = (wrp << 3) + rr2;
        float a0 = sp[row][lane], a1 = sp[row][lane + 32];
        float mx = fmaxf(a0, a1);
        #pragma unroll
        for (int o = 16; o; o >>= 1) mx = fmaxf(mx, __shfl_xor_sync(~0u, mx, o));
        float e0 = __expf(a0 - mx), e1 = __expf(a1 - mx);
        float sm = e0 + e1;
        #pragma unroll
        for (int o = 16; o; o >>= 1) sm += __shfl_xor_sync(~0u, sm, o);
        float inv = 1.0f / sm;
        sp[row][lane] = e0 * inv; sp[row][lane + 32] = e1 * inv;
    }
    __syncthreads();
    float acc[8] = {};
    for (int m = 0; m < 64; m++) {
        float vv = sv[m][lane];
        #pragma unroll
        for (int nn = 0; nn < 8; nn++)
            acc[nn] = fmaf(sp[(wrp << 3) + nn][m], vv, acc[nn]);
    }
    float* ob = g_att + (size_t)win * NTOK * CH + head * HDIM;
    #pragma unroll
    for (int nn = 0; nn < 8; nn++)
        ob[(size_t)((wrp << 3) + nn) * CH + lane] = acc[nn];
}

// ---------------- depthwise 9x9 conv + unfold, accumulated into g_att ----------------
__global__ __launch_bounds__(256) void gaze_conv_kernel(const float* __restrict__ gw,
                                                        const float* __restrict__ gb) {
    int bidx = blockIdx.x;
    int cc = bidx & 7;
    int tile = (bidx >> 3) & 63;
    int b = bidx >> 9;
    int tr = (tile >> 3) << 3;
    int tc = (tile & 7) << 3;
    int ch0 = cc << 5;

    __shared__ float sin_[16][16][32];
    __shared__ float swt[81][32];
    int tid = threadIdx.x;

    for (int i = tid; i < 81 * 32; i += 256) {
        int tap = i >> 5, ch = i & 31;
        swt[tap][ch] = gw[tap * CH + ch0 + ch];
    }
    for (int i = tid; i < 16 * 16 * 32; i += 256) {
        int ch = i & 31, px = (i >> 5) & 15, py = i >> 9;
        int R = tr - 4 + py, Cc = tc - 4 + px;
        float v = 0.f;
        if (R >= 0 && R < 64 && Cc >= 0 && Cc < 64)
            v = g_img[(((size_t)((b << 6) + R) << 6) + Cc) * CH + ch0 + ch];
        sin_[py][px][ch] = v;
    }
    __syncthreads();

    int ch = tid & 31, px = tid >> 5;
    float acc[8] = {};
    #pragma unroll
    for (int dx = 0; dx < 9; dx++) {
        float col[16];
        #pragma unroll
        for (int ry = 0; ry < 16; ry++) col[ry] = sin_[ry][px + dx][ch];
        #pragma unroll
        for (int dy = 0; dy < 9; dy++) {
            float wv = swt[dy * 9 + dx][ch];
            #pragma unroll
            for (int py = 0; py < 8; py++) acc[py] = fmaf(col[py + dy], wv, acc[py]);
        }
    }
    float bias = gb[ch0 + ch];
    #pragma unroll
    for (int py = 0; py < 8; py++) {
        int R = tr + py, Cc = tc + px;
        int wh = R & 7, ii = R >> 3, ww = Cc & 7, jj = Cc >> 3;
        int r = ((b * 64 + wh * 8 + ww) << 6) + (ii << 3) + jj;
        size_t o = (size_t)r * CH + ch0 + ch;
        g_att[o] += acc[py] + bias;
    }
}

// ---------------- final transpose: y (token-major) -> NCHW out ----------------
__global__ __launch_bounds__(256) void out_transpose(float* __restrict__ out) {
    __shared__ float t[32][33];
    int tb = blockIdx.x;
    int cb = blockIdx.y;
    int txi = threadIdx.x, tyi = threadIdx.y;
    int t0 = tb * 32;
    #pragma unroll
    for (int i = 0; i < 4; i++) {
        int tok = t0 + tyi + i * 8;
        t[tyi + i * 8][txi] = g_xnw[(size_t)tok * CH + cb * 32 + txi];
    }
    __syncthreads();
    int b = t0 >> 12, hw0 = t0 & 4095;
    #pragma unroll
    for (int i = 0; i < 4; i++) {
        int ch = cb * 32 + tyi + i * 8;
        out[((size_t)(b * CH + ch) << 12) + hw0 + txi] = t[txi][tyi + i * 8];
    }
}

// ---------------- host launch ----------------
extern "C" void kernel_launch(void* const* d_in, const int* in_sizes, int n_in,
                              void* d_out, int out_size) {
    int off = (n_in >= 18) ? 2 : 0;
    const float* x       = (const float*)d_in[off + 0];
    const float* norm1_g = (const float*)d_in[off + 1];
    const float* norm1_b = (const float*)d_in[off + 2];
    const float* qkv_w   = (const float*)d_in[off + 3];
    const float* qkv_b   = (const float*)d_in[off + 4];
    const float* rpb     = (const float*)d_in[off + 5];
    const float* proj_w  = (const float*)d_in[off + 6];
    const float* proj_b  = (const float*)d_in[off + 7];
    const float* gaze_w  = (const float*)d_in[off + 8];
    const float* gaze_b  = (const float*)d_in[off + 9];
    const float* norm2_g = (const float*)d_in[off + 10];
    const float* norm2_b = (const float*)d_in[off + 11];
    const float* fc1_w   = (const float*)d_in[off + 12];
    const float* fc1_b   = (const float*)d_in[off + 13];
    const float* fc2_w   = (const float*)d_in[off + 14];
    const float* fc2_b   = (const float*)d_in[off + 15];

    float *p_xnw, *p_att, *p_ln2, *p_h1;
    cudaGetSymbolAddress((void**)&p_xnw, g_xnw);
    cudaGetSymbolAddress((void**)&p_att, g_att);
    cudaGetSymbolAddress((void**)&p_ln2, g_ln2);
    cudaGetSymbolAddress((void**)&p_h1,  g_h1);

    bias_kernel<<<128, 256>>>(rpb);
    ln1_kernel<<<2048, 256>>>(x, norm1_g, norm1_b);
    hgemm<EpiQKV><<<dim3(6, 512), 256>>>(p_xnw, qkv_w, 256, EpiQKV{qkv_b});
    attn_kernel<<<8192, 256>>>();
    gaze_conv_kernel<<<8192, 256>>>(gaze_w, gaze_b);
    hgemm<EpiProj><<<dim3(2, 512), 256>>>(p_att, proj_w, 256, EpiProj{proj_b});
    ln2_kernel<<<TOKENS, 256>>>(norm2_g, norm2_b);
    hgemm<EpiFC1><<<dim3(8, 512), 256>>>(p_ln2, fc1_w, 256, EpiFC1{fc1_b});
    hgemm<EpiFC2><<<dim3(2, 512), 256>>>(p_h1, fc2_w, 1024, EpiFC2{fc2_b});
    out_transpose<<<dim3(2048, 8), dim3(32, 8)>>>((float*)d_out);
}

// round 4
// speedup vs baseline: 3.6298x; 1.5659x over previous
#include <cuda_runtime.h>
#include <cuda_fp16.h>
#include <math.h>
#include <stdint.h>

#define BATCH   16
#define CH      256
#define TOKENS  (BATCH*64*64)      // 65536
#define HID     1024
#define NHEAD   8
#define NTOK    64

// ---------------- scratch (device globals; allocation-free) ----------------
__device__ float  g_xf  [TOKENS*CH];   // shortcut, token-major (fp32)
__device__ float  g_xf2 [TOKENS*CH];   // after proj residual, token-major (fp32)
__device__ float  g_y   [TOKENS*CH];   // final token-major result (fp32)
__device__ float  g_att [TOKENS*CH];   // attn out fp32 (pre-gaze), windowed-row-major
__device__ float  g_bias[NHEAD*NTOK*NTOK];

__device__ __half g_xnw_h[TOKENS*CH];  // LN1 out, windowed
__device__ __half g_q   [TOKENS*CH];   // [win][head][pos][hd], pre-scaled
__device__ __half g_k   [TOKENS*CH];
__device__ __half g_v   [TOKENS*CH];
__device__ __half g_img_h[TOKENS*CH];  // folded image NHWC
__device__ __half g_att_h[TOKENS*CH];  // attn+gaze, windowed (proj A operand)
__device__ __half g_ln2_h[TOKENS*CH];
__device__ __half g_h1_h [TOKENS*HID];

__device__ __half w_qkv [768*256];
__device__ __half w_proj[256*256];
__device__ __half w_fc1 [1024*256];
__device__ __half w_fc2 [256*1024];

// ============================ helpers ============================
__device__ __forceinline__ uint32_t smem_u32(const void* p) {
    uint32_t a;
    asm("{ .reg .u64 t; cvta.to.shared.u64 t, %1; cvt.u32.u64 %0, t; }" : "=r"(a) : "l"(p));
    return a;
}
__device__ __forceinline__ uint32_t f2h2(float a, float b) {
    __half2 h = __floats2half2_rn(a, b);
    return *reinterpret_cast<uint32_t*>(&h);
}
__device__ __forceinline__ void ldsm4(uint32_t (&r)[4], uint32_t addr) {
    asm volatile("ldmatrix.sync.aligned.m8n8.x4.shared.b16 {%0,%1,%2,%3}, [%4];"
                 : "=r"(r[0]), "=r"(r[1]), "=r"(r[2]), "=r"(r[3]) : "r"(addr));
}
__device__ __forceinline__ void ldsm4t(uint32_t (&r)[4], uint32_t addr) {
    asm volatile("ldmatrix.sync.aligned.m8n8.x4.trans.shared.b16 {%0,%1,%2,%3}, [%4];"
                 : "=r"(r[0]), "=r"(r[1]), "=r"(r[2]), "=r"(r[3]) : "r"(addr));
}
__device__ __forceinline__ void mma16816(float* d, const uint32_t* a, uint32_t b0, uint32_t b1) {
    asm volatile("mma.sync.aligned.m16n8k16.row.col.f32.f16.f16.f32 "
                 "{%0,%1,%2,%3},{%4,%5,%6,%7},{%8,%9},{%0,%1,%2,%3};"
                 : "+f"(d[0]), "+f"(d[1]), "+f"(d[2]), "+f"(d[3])
                 : "r"(a[0]), "r"(a[1]), "r"(a[2]), "r"(a[3]), "r"(b0), "r"(b1));
}
#define CP_A16(dst, src) asm volatile("cp.async.cg.shared.global [%0], [%1], 16;" :: "r"(dst), "l"(src))
#define CP_COMMIT()      asm volatile("cp.async.commit_group;")
#define CP_WAIT(n)       asm volatile("cp.async.wait_group %0;" :: "n"(n))

// ============================ fp16 GEMM, cp.async 3-stage ============================
// C[m][n] = sum_k A[m][k]*W[n][k].  BM=BN=128, BK=32, 256 thr, warp tile 64x32.
#define LDSTR 40
#define SSZ   (128*LDSTR)                 // halves per tensor per stage
#define SMEM_DYN (3*2*SSZ*2)              // 61440 bytes

template <class Epi>
__global__ __launch_bounds__(256) void hgemm(const __half* __restrict__ A,
                                             const __half* __restrict__ W,
                                             int K, Epi epi) {
    extern __shared__ __half sm[];
    int tid = threadIdx.x, lane = tid & 31, wid = tid >> 5;
    int wm = wid >> 2, wn = wid & 3;
    int bm = blockIdx.y << 7, bn = blockIdx.x << 7;
    int NC = K >> 5;
    uint32_t smb = smem_u32(sm);

    auto issue = [&](int st, int ic) {
        int k0 = ic << 5;
        uint32_t sb = smb + st * (2 * SSZ) * 2;
        #pragma unroll
        for (int j = 0; j < 2; j++) {
            int ch = tid + (j << 8);
            int row = ch >> 2, cq = ch & 3;
            uint32_t da = sb + (row * LDSTR + cq * 8) * 2;
            CP_A16(da, A + (size_t)(bm + row) * K + k0 + cq * 8);
            CP_A16(da + SSZ * 2, W + (size_t)(bn + row) * K + k0 + cq * 8);
        }
        CP_COMMIT();
    };

    issue(0, 0); issue(1, 1);
    float acc[4][4][4] = {};
    for (int ic = 0; ic < NC; ic++) {
        if (ic + 1 < NC) CP_WAIT(1); else CP_WAIT(0);
        __syncthreads();
        if (ic + 2 < NC) issue((ic + 2) % 3, ic + 2);
        uint32_t baseA = smb + (ic % 3) * (2 * SSZ) * 2;
        uint32_t baseB = baseA + SSZ * 2;
        #pragma unroll
        for (int ks = 0; ks < 2; ks++) {
            uint32_t af[4][4], bf[2][4];
            #pragma unroll
            for (int mt = 0; mt < 4; mt++)
                ldsm4(af[mt], baseA + (((wm*64 + mt*16 + (lane & 15)) * LDSTR + ks*16 + (lane >> 4)*8) << 1));
            #pragma unroll
            for (int bt = 0; bt < 2; bt++)
                ldsm4(bf[bt], baseB + (((wn*32 + bt*16 + (lane & 15)) * LDSTR + ks*16 + (lane >> 4)*8) << 1));
            #pragma unroll
            for (int mt = 0; mt < 4; mt++)
                #pragma unroll
                for (int nt = 0; nt < 4; nt++)
                    mma16816(acc[mt][nt], af[mt], bf[nt>>1][nt&1], bf[nt>>1][(nt&1)+2]);
        }
    }
    int g = lane >> 2, tg = lane & 3;
    #pragma unroll
    for (int mt = 0; mt < 4; mt++) {
        int M0 = bm + wm * 64 + mt * 16;
        #pragma unroll
        for (int nt = 0; nt < 4; nt++) {
            int N0 = bn + wn * 32 + nt * 8;
            float* d = acc[mt][nt];
            epi(M0 + g,     N0 + tg*2,     d[0]);
            epi(M0 + g,     N0 + tg*2 + 1, d[1]);
            epi(M0 + g + 8, N0 + tg*2,     d[2]);
            epi(M0 + g + 8, N0 + tg*2 + 1, d[3]);
        }
    }
}

// ============================ epilogues ============================
struct EpiQKV {
    const float* bias;
    __device__ void operator()(int r, int c, float acc) const {
        float val = acc + bias[c];
        int part = c >> 8, head = (c >> 5) & 7, d = c & 31;
        int win = r >> 6, pos = r & 63;
        size_t o = (size_t)(win * NHEAD + head) * 2048 + pos * 32 + d;
        if (part == 0)      g_q[o] = __float2half(val * 4.0f);
        else if (part == 1) g_k[o] = __float2half(val);
        else {
            __half hv = __float2half(val);
            g_v[o] = hv;
            int b = win >> 6, wh = (win >> 3) & 7, ww = win & 7;
            int ii = pos >> 3, jj = pos & 7;
            int R = ii * 8 + wh, Cc = jj * 8 + ww;
            g_img_h[(((size_t)((b << 6) + R) << 6) + Cc) * CH + (c - 512)] = hv;
        }
    }
};
struct EpiProj {
    const float* bias;
    __device__ void operator()(int r, int c, float acc) const {
        float val = acc + bias[c];
        int win = r >> 6, pos = r & 63;
        int b = win >> 6, wh = (win >> 3) & 7, ww = win & 7;
        int ii = pos >> 3, jj = pos & 7;
        int t = (b << 12) + ((wh * 8 + ii) << 6) + ww * 8 + jj;
        size_t o = (size_t)t * CH + c;
        g_xf2[o] = g_xf[o] + val;
    }
};
struct EpiFC1 {
    const float* bias;
    __device__ void operator()(int r, int c, float acc) const {
        float x = acc + bias[c];
        g_h1_h[(size_t)r * HID + c] = __float2half(0.5f * x * (1.0f + erff(x * 0.70710678118654752f)));
    }
};
struct EpiFC2 {
    const float* bias;
    __device__ void operator()(int r, int c, float acc) const {
        g_y[(size_t)r * CH + c] = acc + bias[c] + g_xf2[(size_t)r * CH + c];
    }
};

// ---------------- weight fp32 -> fp16 ----------------
__global__ void cvt_half(const float* __restrict__ s, __half* __restrict__ d, int n) {
    int i = blockIdx.x * 256 + threadIdx.x;
    if (i < n) d[i] = __float2half(s[i]);
}

// ---------------- relative position bias prep ----------------
__global__ void bias_kernel(const float* __restrict__ rpb) {
    int idx = blockIdx.x * 256 + threadIdx.x;
    int h_ = idx >> 12, n = (idx >> 6) & 63, m = idx & 63;
    int di = (n >> 3) - (m >> 3) + 7;
    int dj = (n & 7) - (m & 7) + 7;
    g_bias[idx] = rpb[(di * 15 + dj) * NHEAD + h_];
}

// ---------------- LayerNorm 1 ----------------
__global__ __launch_bounds__(256) void ln1_kernel(const float* __restrict__ x,
                                                  const float* __restrict__ gw,
                                                  const float* __restrict__ gb) {
    __shared__ float tx[256][33];
    int t0 = blockIdx.x * 32;
    int b = t0 >> 12, hw0 = t0 & 4095;
    int tid = threadIdx.x;
    #pragma unroll
    for (int j = 0; j < 32; j++) {
        int idx = j * 256 + tid;
        int c = idx >> 5, i = idx & 31;
        tx[c][i] = x[((size_t)(b * CH + c) << 12) + hw0 + i];
    }
    __syncthreads();
    int lane = tid & 31, w = tid >> 5;
    #pragma unroll
    for (int q = 0; q < 4; q++) {
        int i = w * 4 + q;
        float s = 0.f, s2 = 0.f;
        #pragma unroll
        for (int k = 0; k < 8; k++) { float v = tx[lane + 32 * k][i]; s += v; s2 += v * v; }
        #pragma unroll
        for (int o = 16; o; o >>= 1) { s += __shfl_xor_sync(~0u, s, o); s2 += __shfl_xor_sync(~0u, s2, o); }
        float mean = s * (1.f / CH);
        float inv = rsqrtf(s2 * (1.f / CH) - mean * mean + 1e-5f);
        int t = t0 + i;
        int hw = hw0 + i, hh = hw >> 6, wc = hw & 63;
        int wh = hh >> 3, ii = hh & 7, ww = wc >> 3, jj = wc & 7;
        int r = ((b * 64 + wh * 8 + ww) << 6) + (ii << 3) + jj;
        #pragma unroll
        for (int k = 0; k < 8; k++) {
            int c = lane + 32 * k;
            float v = tx[c][i];
            g_xf[(size_t)t * CH + c] = v;
            g_xnw_h[(size_t)r * CH + c] = __float2half((v - mean) * inv * gw[c] + gb[c]);
        }
    }
}

// ---------------- LayerNorm 2 ----------------
__global__ __launch_bounds__(256) void ln2_kernel(const float* __restrict__ gw,
                                                  const float* __restrict__ gb) {
    int t = blockIdx.x, c = threadIdx.x;
    float val = g_xf2[(size_t)t * CH + c];
    __shared__ float sh1[8], sh2[8], sres[2];
    float s = val, s2 = val * val;
    #pragma unroll
    for (int o = 16; o; o >>= 1) { s += __shfl_xor_sync(~0u, s, o); s2 += __shfl_xor_sync(~0u, s2, o); }
    int lane = c & 31, wrp = c >> 5;
    if (!lane) { sh1[wrp] = s; sh2[wrp] = s2; }
    __syncthreads();
    if (!wrp) {
        s = lane < 8 ? sh1[lane] : 0.f;
        s2 = lane < 8 ? sh2[lane] : 0.f;
        #pragma unroll
        for (int o = 4; o; o >>= 1) { s += __shfl_xor_sync(~0u, s, o); s2 += __shfl_xor_sync(~0u, s2, o); }
        if (!lane) { sres[0] = s; sres[1] = s2; }
    }
    __syncthreads();
    float mean = sres[0] * (1.f / CH);
    float var = sres[1] * (1.f / CH) - mean * mean;
    g_ln2_h[(size_t)t * CH + c] = __float2half((val - mean) * rsqrtf(var + 1e-5f) * gw[c] + gb[c]);
}

// ---------------- tensor-core attention: one block per (win, head), 4 warps ----------------
__global__ __launch_bounds__(128) void attn_mma() {
    int win = blockIdx.x >> 3, head = blockIdx.x & 7;
    __shared__ __half sq[64 * 40], sk[64 * 40], sv[64 * 40];
    __shared__ float sb[64 * 64];
    int tid = threadIdx.x, lane = tid & 31, w = tid >> 5;

    const __half* qb = g_q + (size_t)(win * NHEAD + head) * 2048;
    const __half* kb = g_k + (size_t)(win * NHEAD + head) * 2048;
    const __half* vb = g_v + (size_t)(win * NHEAD + head) * 2048;
    #pragma unroll
    for (int j = 0; j < 2; j++) {
        int ch = tid + (j << 7);
        int row = ch >> 2, cq = ch & 3;
        *(uint4*)&sq[row * 40 + cq * 8] = *(const uint4*)(qb + row * 32 + cq * 8);
        *(uint4*)&sk[row * 40 + cq * 8] = *(const uint4*)(kb + row * 32 + cq * 8);
        *(uint4*)&sv[row * 40 + cq * 8] = *(const uint4*)(vb + row * 32 + cq * 8);
    }
    const float4* bb = (const float4*)(g_bias + head * 4096);
    #pragma unroll
    for (int j = 0; j < 8; j++)
        ((float4*)sb)[tid + (j << 7)] = bb[tid + (j << 7)];
    __syncthreads();

    uint32_t bq = smem_u32(sq), bk = smem_u32(sk), bv = smem_u32(sv);
    int g = lane >> 2, tg = lane & 3;

    uint32_t aq[2][4];
    #pragma unroll
    for (int t = 0; t < 2; t++)
        ldsm4(aq[t], bq + (((16 * w + (lane & 15)) * 40 + t * 16 + (lane >> 4) * 8) << 1));

    float acc[8][4] = {};
    #pragma unroll
    for (int t = 0; t < 2; t++)
        #pragma unroll
        for (int u = 0; u < 4; u++) {
            uint32_t bf[4];
            ldsm4(bf, bk + (((16 * u + (lane & 15)) * 40 + t * 16 + (lane >> 4) * 8) << 1));
            mma16816(acc[2 * u],     aq[t], bf[0], bf[2]);
            mma16816(acc[2 * u + 1], aq[t], bf[1], bf[3]);
        }

    // + bias, softmax over the 64 columns (rows g and g+8 of this warp's 16)
    int r0 = 16 * w + g, r1 = r0 + 8;
    float mx0 = -1e30f, mx1 = -1e30f;
    #pragma unroll
    for (int s = 0; s < 8; s++) {
        acc[s][0] += sb[r0 * 64 + 8 * s + tg * 2];
        acc[s][1] += sb[r0 * 64 + 8 * s + tg * 2 + 1];
        acc[s][2] += sb[r1 * 64 + 8 * s + tg * 2];
        acc[s][3] += sb[r1 * 64 + 8 * s + tg * 2 + 1];
        mx0 = fmaxf(mx0, fmaxf(acc[s][0], acc[s][1]));
        mx1 = fmaxf(mx1, fmaxf(acc[s][2], acc[s][3]));
    }
    mx0 = fmaxf(mx0, __shfl_xor_sync(~0u, mx0, 1)); mx0 = fmaxf(mx0, __shfl_xor_sync(~0u, mx0, 2));
    mx1 = fmaxf(mx1, __shfl_xor_sync(~0u, mx1, 1)); mx1 = fmaxf(mx1, __shfl_xor_sync(~0u, mx1, 2));
    float sm0 = 0.f, sm1 = 0.f;
    #pragma unroll
    for (int s = 0; s < 8; s++) {
        acc[s][0] = __expf(acc[s][0] - mx0); acc[s][1] = __expf(acc[s][1] - mx0);
        acc[s][2] = __expf(acc[s][2] - mx1); acc[s][3] = __expf(acc[s][3] - mx1);
        sm0 += acc[s][0] + acc[s][1];
        sm1 += acc[s][2] + acc[s][3];
    }
    sm0 += __shfl_xor_sync(~0u, sm0, 1); sm0 += __shfl_xor_sync(~0u, sm0, 2);
    sm1 += __shfl_xor_sync(~0u, sm1, 1); sm1 += __shfl_xor_sync(~0u, sm1, 2);
    float iv0 = 1.f / sm0, iv1 = 1.f / sm1;
    uint32_t ap[4][4];
    #pragma unroll
    for (int t = 0; t < 4; t++) {
        ap[t][0] = f2h2(acc[2*t][0]*iv0,   acc[2*t][1]*iv0);
        ap[t][1] = f2h2(acc[2*t][2]*iv1,   acc[2*t][3]*iv1);
        ap[t][2] = f2h2(acc[2*t+1][0]*iv0, acc[2*t+1][1]*iv0);
        ap[t][3] = f2h2(acc[2*t+1][2]*iv1, acc[2*t+1][3]*iv1);
    }

    float oacc[4][4] = {};
    #pragma unroll
    for (int t = 0; t < 4; t++)
        #pragma unroll
        for (int np = 0; np < 2; np++) {
            uint32_t bf[4];
            ldsm4t(bf, bv + (((16 * t + (lane & 15)) * 40 + np * 16 + (lane >> 4) * 8) << 1));
            mma16816(oacc[2 * np],     ap[t], bf[0], bf[1]);
            mma16816(oacc[2 * np + 1], ap[t], bf[2], bf[3]);
        }

    float* ob = g_att + ((size_t)win * 64) * 256 + head * 32;
    #pragma unroll
    for (int n = 0; n < 4; n++) {
        *(float2*)&ob[(size_t)r0 * 256 + 8 * n + tg * 2] = make_float2(oacc[n][0], oacc[n][1]);
        *(float2*)&ob[(size_t)r1 * 256 + 8 * n + tg * 2] = make_float2(oacc[n][2], oacc[n][3]);
    }
}

// ---------------- depthwise 9x9 conv + unfold; writes half(attn + gaze) ----------------
__global__ __launch_bounds__(256) void gaze_conv_kernel(const float* __restrict__ gw,
                                                        const float* __restrict__ gb) {
    int bidx = blockIdx.x;                 // 16*64*8
    int cc = bidx & 7;
    int tile = (bidx >> 3) & 63;
    int b = bidx >> 9;
    int tr = (tile >> 3) << 3;
    int tc = (tile & 7) << 3;
    int ch0 = cc << 5;

    __shared__ float sin_[16][16][32];
    __shared__ float swt[81][32];
    int tid = threadIdx.x;

    for (int i = tid; i < 81 * 32; i += 256) {
        int tap = i >> 5, ch = i & 31;
        swt[tap][ch] = gw[tap * CH + ch0 + ch];
    }
    for (int i = tid; i < 16 * 16 * 32; i += 256) {
        int ch = i & 31, px = (i >> 5) & 15, py = i >> 9;
        int R = tr - 4 + py, Cc = tc - 4 + px;
        float v = 0.f;
        if (R >= 0 && R < 64 && Cc >= 0 && Cc < 64)
            v = __half2float(g_img_h[(((size_t)((b << 6) + R) << 6) + Cc) * CH + ch0 + ch]);
        sin_[py][px][ch] = v;
    }
    __syncthreads();

    int ch = tid & 31, px = tid >> 5;
    float acc[8] = {};
    #pragma unroll
    for (int dx = 0; dx < 9; dx++) {
        float col[16];
        #pragma unroll
        for (int ry = 0; ry < 16; ry++) col[ry] = sin_[ry][px + dx][ch];
        #pragma unroll
        for (int dy = 0; dy < 9; dy++) {
            float wv = swt[dy * 9 + dx][ch];
            #pragma unroll
            for (int py = 0; py < 8; py++) acc[py] = fmaf(col[py + dy], wv, acc[py]);
        }
    }
    float bias = gb[ch0 + ch];
    #pragma unroll
    for (int py = 0; py < 8; py++) {
        int R = tr + py, Cc = tc + px;
        int wh = R & 7, ii = R >> 3, ww = Cc & 7, jj = Cc >> 3;
        int r = ((b * 64 + wh * 8 + ww) << 6) + (ii << 3) + jj;
        size_t o = (size_t)r * CH + ch0 + ch;
        g_att_h[o] = __float2half(g_att[o] + acc[py] + bias);
    }
}

// ---------------- final transpose: y (token-major) -> NCHW out ----------------
__global__ __launch_bounds__(256) void out_transpose(float* __restrict__ out) {
    __shared__ float t[32][33];
    int tb = blockIdx.x;
    int cb = blockIdx.y;
    int txi = threadIdx.x, tyi = threadIdx.y;
    int t0 = tb * 32;
    #pragma unroll
    for (int i = 0; i < 4; i++) {
        int tok = t0 + tyi + i * 8;
        t[tyi + i * 8][txi] = g_y[(size_t)tok * CH + cb * 32 + txi];
    }
    __syncthreads();
    int b = t0 >> 12, hw0 = t0 & 4095;
    #pragma unroll
    for (int i = 0; i < 4; i++) {
        int ch = cb * 32 + tyi + i * 8;
        out[((size_t)(b * CH + ch) << 12) + hw0 + txi] = t[txi][tyi + i * 8];
    }
}

// ---------------- host launch ----------------
extern "C" void kernel_launch(void* const* d_in, const int* in_sizes, int n_in,
                              void* d_out, int out_size) {
    int off = (n_in >= 18) ? 2 : 0;
    const float* x       = (const float*)d_in[off + 0];
    const float* norm1_g = (const float*)d_in[off + 1];
    const float* norm1_b = (const float*)d_in[off + 2];
    const float* qkv_w   = (const float*)d_in[off + 3];
    const float* qkv_b   = (const float*)d_in[off + 4];
    const float* rpb     = (const float*)d_in[off + 5];
    const float* proj_w  = (const float*)d_in[off + 6];
    const float* proj_b  = (const float*)d_in[off + 7];
    const float* gaze_w  = (const float*)d_in[off + 8];
    const float* gaze_b  = (const float*)d_in[off + 9];
    const float* norm2_g = (const float*)d_in[off + 10];
    const float* norm2_b = (const float*)d_in[off + 11];
    const float* fc1_w   = (const float*)d_in[off + 12];
    const float* fc1_b   = (const float*)d_in[off + 13];
    const float* fc2_w   = (const float*)d_in[off + 14];
    const float* fc2_b   = (const float*)d_in[off + 15];

    __half *pw_qkv, *pw_proj, *pw_fc1, *pw_fc2;
    __half *p_xnw, *p_atth, *p_ln2, *p_h1;
    cudaGetSymbolAddress((void**)&pw_qkv, w_qkv);
    cudaGetSymbolAddress((void**)&pw_proj, w_proj);
    cudaGetSymbolAddress((void**)&pw_fc1, w_fc1);
    cudaGetSymbolAddress((void**)&pw_fc2, w_fc2);
    cudaGetSymbolAddress((void**)&p_xnw, g_xnw_h);
    cudaGetSymbolAddress((void**)&p_atth, g_att_h);
    cudaGetSymbolAddress((void**)&p_ln2, g_ln2_h);
    cudaGetSymbolAddress((void**)&p_h1,  g_h1_h);

    cudaFuncSetAttribute(hgemm<EpiQKV>, cudaFuncAttributeMaxDynamicSharedMemorySize, SMEM_DYN);
    cudaFuncSetAttribute(hgemm<EpiProj>, cudaFuncAttributeMaxDynamicSharedMemorySize, SMEM_DYN);
    cudaFuncSetAttribute(hgemm<EpiFC1>, cudaFuncAttributeMaxDynamicSharedMemorySize, SMEM_DYN);
    cudaFuncSetAttribute(hgemm<EpiFC2>, cudaFuncAttributeMaxDynamicSharedMemorySize, SMEM_DYN);

    cvt_half<<<768, 256>>>(qkv_w, pw_qkv, 768 * 256);
    cvt_half<<<256, 256>>>(proj_w, pw_proj, 256 * 256);
    cvt_half<<<1024, 256>>>(fc1_w, pw_fc1, 1024 * 256);
    cvt_half<<<1024, 256>>>(fc2_w, pw_fc2, 256 * 1024);
    bias_kernel<<<128, 256>>>(rpb);
    ln1_kernel<<<2048, 256>>>(x, norm1_g, norm1_b);
    hgemm<EpiQKV><<<dim3(6, 512), 256, SMEM_DYN>>>(p_xnw, pw_qkv, 256, EpiQKV{qkv_b});
    attn_mma<<<8192, 128>>>();
    gaze_conv_kernel<<<8192, 256>>>(gaze_w, gaze_b);
    hgemm<EpiProj><<<dim3(2, 512), 256, SMEM_DYN>>>(p_atth, pw_proj, 256, EpiProj{proj_b});
    ln2_kernel<<<TOKENS, 256>>>(norm2_g, norm2_b);
    hgemm<EpiFC1><<<dim3(8, 512), 256, SMEM_DYN>>>(p_ln2, pw_fc1, 256, EpiFC1{fc1_b});
    hgemm<EpiFC2><<<dim3(2, 512), 256, SMEM_DYN>>>(p_h1, pw_fc2, 1024, EpiFC2{fc2_b});
    out_transpose<<<dim3(2048, 8), dim3(32, 8)>>>((float*)d_out);
}